// round 13
// baseline (speedup 1.0000x reference)
#include <cuda_runtime.h>
#include <cuda_fp16.h>
#include <cstdint>
#include <cstddef>

// Problem dims (fixed by the dataset)
#define M_TOT 4096      // 2*2048
#define N_TOT 16384
#define K_TOT 4096

#define BM 128
#define BN 128
#define BK 64
#define NKT (K_TOT / BK)        // 64
#define NSTAGE 3

#define LDSH 72                 // halves per smem row (64 + 8 pad) -> 144B stride
#define A_STAGE_BYTES (BM * LDSH * 2)   // 18432
#define B_STAGE_BYTES (BN * LDSH * 2)   // 18432
#define STAGE_BYTES   (A_STAGE_BYTES + B_STAGE_BYTES)   // 36864
#define DSMEM_BYTES   (NSTAGE * STAGE_BYTES)            // 110592; 2 CTAs = 221184 <= 228KB

// Static scratch (allocation-free rule: __device__ globals are allowed)
__device__ __half g_w[(size_t)N_TOT * K_TOT];   // 128 MB fp16 (q - zp)
__device__ __half g_x[(size_t)M_TOT * K_TOT];   // 32 MB  fp16 x

// ---------------------------------------------------------------------------
// Prep kernels (MLP=4: four independent 16B loads in flight per thread)
// ---------------------------------------------------------------------------
__global__ void conv_x_kernel(const float* __restrict__ x) {
    const size_t n4 = (size_t)M_TOT * K_TOT / 4;        // 4M float4 chunks
    size_t base = (size_t)blockIdx.x * 1024 + threadIdx.x;
    float4 v[4];
#pragma unroll
    for (int j = 0; j < 4; j++) {
        size_t i = base + j * 256;
        if (i < n4) v[j] = ((const float4*)x)[i];
    }
#pragma unroll
    for (int j = 0; j < 4; j++) {
        size_t i = base + j * 256;
        if (i < n4) {
            ((__half2*)g_x)[i * 2 + 0] = __floats2half2_rn(v[j].x, v[j].y);
            ((__half2*)g_x)[i * 2 + 1] = __floats2half2_rn(v[j].z, v[j].w);
        }
    }
}

__global__ void conv_w_kernel(const int* __restrict__ q, const float* __restrict__ zp_p) {
    const size_t n4 = (size_t)N_TOT * K_TOT / 4;        // 16M int4 chunks
    const float zp = *zp_p;
    size_t base = (size_t)blockIdx.x * 1024 + threadIdx.x;
    int4 v[4];
#pragma unroll
    for (int j = 0; j < 4; j++) {
        size_t i = base + j * 256;
        if (i < n4) v[j] = ((const int4*)q)[i];
    }
#pragma unroll
    for (int j = 0; j < 4; j++) {
        size_t i = base + j * 256;
        if (i < n4) {
            ((__half2*)g_w)[i * 2 + 0] =
                __floats2half2_rn((float)v[j].x - zp, (float)v[j].y - zp);
            ((__half2*)g_w)[i * 2 + 1] =
                __floats2half2_rn((float)v[j].z - zp, (float)v[j].w - zp);
        }
    }
}

// ---------------------------------------------------------------------------
// Helpers
// ---------------------------------------------------------------------------
__device__ __forceinline__ void cp_async_16(uint32_t smem, const void* g) {
    asm volatile("cp.async.cg.shared.global [%0], [%1], 16;\n" :: "r"(smem), "l"(g));
}
__device__ __forceinline__ void cp_commit() {
    asm volatile("cp.async.commit_group;\n" ::);
}

// ---------------------------------------------------------------------------
// HMMA GEMM: out[M,N] = scale * (Xh[M,K] @ Wh[N,K]^T) + bias[n]
// CTA 128x128 (256 thr, 8 warps of 64x32), BK=64, 3 stages, 2 CTAs/SM,
// one barrier per kt, prefetch distance 2. B fragments via ldmatrix.x4.
// ---------------------------------------------------------------------------
__global__ __launch_bounds__(256, 2)
void gemm_kernel(const float* __restrict__ scale_p,
                 const float* __restrict__ bias,
                 float* __restrict__ out) {
    extern __shared__ char dsm[];
    const uint32_t sm_base = (uint32_t)__cvta_generic_to_shared(dsm);

    const int tid  = threadIdx.x;
    const int lane = tid & 31;
    const int warp = tid >> 5;
    const int wm = warp & 1;     // 0..1 -> 64-row slices
    const int wn = warp >> 1;    // 0..3 -> 32-col slices

    const int bid   = blockIdx.x;
    const int mTile = bid & (M_TOT / BM - 1);   // 32 m-tiles, fastest
    const int nTile = bid >> 5;                 // 128 n-tiles
    const int m0 = mTile * BM;
    const int n0 = nTile * BN;

    float acc[4][4][4];
#pragma unroll
    for (int i = 0; i < 4; i++)
#pragma unroll
        for (int j = 0; j < 4; j++)
#pragma unroll
            for (int k = 0; k < 4; k++) acc[i][j][k] = 0.f;

    const __half* gA = g_x + (size_t)m0 * K_TOT;
    const __half* gB = g_w + (size_t)n0 * K_TOT;

    // Per-thread load coords (16B chunks). A: 1024 chunks, B: 1024 chunks; 256 thr.
    const int ldRow = tid >> 3, ldCc = tid & 7;
    auto load_tile = [&](int kt, int st) {
        const int kh0 = kt * BK;
        const uint32_t aBase = sm_base + st * STAGE_BYTES;
        const uint32_t bBase = aBase + A_STAGE_BYTES;
#pragma unroll
        for (int i = 0; i < 4; i++) {       // A: 128 rows x 8 chunks / 256 thr
            int row = ldRow + i * 32;
            cp_async_16(aBase + row * (LDSH * 2) + ldCc * 16,
                        gA + (size_t)row * K_TOT + kh0 + ldCc * 8);
        }
#pragma unroll
        for (int i = 0; i < 4; i++) {       // B: 128 rows x 8 chunks / 256 thr
            int row = ldRow + i * 32;
            cp_async_16(bBase + row * (LDSH * 2) + ldCc * 16,
                        gB + (size_t)row * K_TOT + kh0 + ldCc * 8);
        }
        cp_commit();
    };

    // Prologue: fill 2 stages (prefetch distance 2)
    load_tile(0, 0);
    load_tile(1, 1);

    // ldmatrix per-thread base offsets (bytes), excluding stage/ks/im offsets
    const uint32_t aLdBase =
        (uint32_t)((wm * 64 + (lane & 15)) * (LDSH * 2) + (lane >> 4) * 16);
    // B x4: lane -> n_rel = ((lane>>3)&1)*8 + (lane&7), k-half = lane>>4
    const uint32_t bLdBase =
        (uint32_t)((wn * 32 + ((lane >> 3) & 1) * 8 + (lane & 7)) * (LDSH * 2) +
                   (lane >> 4) * 16);

    int st = 0;     // stage being consumed
    int pst = 2;    // stage to prefetch into

    for (int kt = 0; kt < NKT; kt++) {
        // Tile kt's loads done (allow 1 newer group outstanding)
        asm volatile("cp.async.wait_group 1;\n" ::);
        __syncthreads();

        // Prefetch kt+2 into stage pst (== stage consumed at kt-1; its reads
        // finished before this iteration's barrier).
        if (kt + 2 < NKT) load_tile(kt + 2, pst);
        else cp_commit();   // keep group accounting uniform

        const uint32_t aStage = sm_base + st * STAGE_BYTES;
        const uint32_t bStage = aStage + A_STAGE_BYTES;

#pragma unroll
        for (int ks = 0; ks < 4; ks++) {
            uint32_t a[4][4];
            uint32_t b[4][2];
#pragma unroll
            for (int im = 0; im < 4; im++) {
                uint32_t addr = aStage + aLdBase + im * 16 * (LDSH * 2) + ks * 32;
                asm volatile("ldmatrix.sync.aligned.m8n8.x4.shared.b16 {%0,%1,%2,%3}, [%4];\n"
                             : "=r"(a[im][0]), "=r"(a[im][1]), "=r"(a[im][2]), "=r"(a[im][3])
                             : "r"(addr));
            }
#pragma unroll
            for (int in2 = 0; in2 < 2; in2++) {
                uint32_t addr = bStage + bLdBase + in2 * 16 * (LDSH * 2) + ks * 32;
                // mats: r0=(n0-7,klo) r1=(n8-15,klo) r2=(n0-7,khi) r3=(n8-15,khi)
                asm volatile("ldmatrix.sync.aligned.m8n8.x4.shared.b16 {%0,%1,%2,%3}, [%4];\n"
                             : "=r"(b[in2 * 2][0]), "=r"(b[in2 * 2 + 1][0]),
                               "=r"(b[in2 * 2][1]), "=r"(b[in2 * 2 + 1][1])
                             : "r"(addr));
            }
#pragma unroll
            for (int im = 0; im < 4; im++) {
#pragma unroll
                for (int in_ = 0; in_ < 4; in_++) {
                    asm volatile(
                        "mma.sync.aligned.m16n8k16.row.col.f32.f16.f16.f32 "
                        "{%0,%1,%2,%3}, {%4,%5,%6,%7}, {%8,%9}, {%0,%1,%2,%3};\n"
                        : "+f"(acc[im][in_][0]), "+f"(acc[im][in_][1]),
                          "+f"(acc[im][in_][2]), "+f"(acc[im][in_][3])
                        : "r"(a[im][0]), "r"(a[im][1]), "r"(a[im][2]), "r"(a[im][3]),
                          "r"(b[in_][0]), "r"(b[in_][1]));
                }
            }
        }

        st  = (st  == NSTAGE - 1) ? 0 : st + 1;
        pst = (pst == NSTAGE - 1) ? 0 : pst + 1;
    }

    // Epilogue: out = scale*acc + bias
    const float s = *scale_p;
    const int mBase = m0 + wm * 64;
    const int nBase = n0 + wn * 32;
#pragma unroll
    for (int im = 0; im < 4; im++) {
#pragma unroll
        for (int in_ = 0; in_ < 4; in_++) {
            int row = mBase + im * 16 + (lane >> 2);
            int col = nBase + in_ * 8 + (lane & 3) * 2;
            float2 bv = *(const float2*)&bias[col];
            float2 o0 = make_float2(s * acc[im][in_][0] + bv.x,
                                    s * acc[im][in_][1] + bv.y);
            float2 o1 = make_float2(s * acc[im][in_][2] + bv.x,
                                    s * acc[im][in_][3] + bv.y);
            *(float2*)&out[(size_t)row * N_TOT + col] = o0;
            *(float2*)&out[(size_t)(row + 8) * N_TOT + col] = o1;
        }
    }
}

// ---------------------------------------------------------------------------
// Launch
// ---------------------------------------------------------------------------
extern "C" void kernel_launch(void* const* d_in, const int* in_sizes, int n_in,
                              void* d_out, int out_size) {
    const float* x     = (const float*)d_in[0];
    const int*   wq    = (const int*)d_in[1];
    const float* scale = (const float*)d_in[2];
    const float* zp    = (const float*)d_in[3];
    const float* bias  = (const float*)d_in[4];
    float* out = (float*)d_out;

    cudaFuncSetAttribute(gemm_kernel, cudaFuncAttributeMaxDynamicSharedMemorySize,
                         DSMEM_BYTES);

    {
        size_t n4 = (size_t)M_TOT * K_TOT / 4;           // 4M chunks, 1024/block
        conv_x_kernel<<<(unsigned)((n4 + 1023) / 1024), 256>>>(x);
    }
    {
        size_t n4 = (size_t)N_TOT * K_TOT / 4;           // 16M chunks, 1024/block
        conv_w_kernel<<<(unsigned)((n4 + 1023) / 1024), 256>>>(wq, zp);
    }
    {
        unsigned grid = (M_TOT / BM) * (N_TOT / BN);     // 32*128 = 4096
        gemm_kernel<<<grid, 256, DSMEM_BYTES>>>(scale, bias, out);
    }
}

// round 14
// speedup vs baseline: 1.0983x; 1.0983x over previous
#include <cuda_runtime.h>
#include <cuda_fp16.h>
#include <cstdint>
#include <cstddef>

// Problem dims (fixed by the dataset)
#define M_TOT 4096      // 2*2048
#define N_TOT 16384
#define K_TOT 4096

#define BM 128
#define BN 128
#define BK 64
#define NKT (K_TOT / BK)        // 64
#define NSTAGE 3

#define LDSH 72                 // halves per smem row (64 + 8 pad) -> 144B stride
#define A_STAGE_BYTES (BM * LDSH * 2)   // 18432
#define B_STAGE_BYTES (BN * LDSH * 2)   // 18432
#define STAGE_BYTES   (A_STAGE_BYTES + B_STAGE_BYTES)   // 36864
#define DSMEM_BYTES   (NSTAGE * STAGE_BYTES)            // 110592; 2 CTAs = 221184 <= 228KB

// Static scratch (allocation-free rule: __device__ globals are allowed)
__device__ __half g_w[(size_t)N_TOT * K_TOT];   // 128 MB fp16 (q - zp)
__device__ __half g_x[(size_t)M_TOT * K_TOT];   // 32 MB  fp16 x

// ---------------------------------------------------------------------------
// Prep kernels (MLP=4: four independent 16B loads in flight per thread)
// ---------------------------------------------------------------------------
__global__ void conv_x_kernel(const float* __restrict__ x) {
    const size_t n4 = (size_t)M_TOT * K_TOT / 4;        // 4M float4 chunks
    size_t base = (size_t)blockIdx.x * 1024 + threadIdx.x;
    float4 v[4];
#pragma unroll
    for (int j = 0; j < 4; j++) {
        size_t i = base + j * 256;
        if (i < n4) v[j] = ((const float4*)x)[i];
    }
#pragma unroll
    for (int j = 0; j < 4; j++) {
        size_t i = base + j * 256;
        if (i < n4) {
            ((__half2*)g_x)[i * 2 + 0] = __floats2half2_rn(v[j].x, v[j].y);
            ((__half2*)g_x)[i * 2 + 1] = __floats2half2_rn(v[j].z, v[j].w);
        }
    }
}

__global__ void conv_w_kernel(const int* __restrict__ q, const float* __restrict__ zp_p) {
    const size_t n4 = (size_t)N_TOT * K_TOT / 4;        // 16M int4 chunks
    const float zp = *zp_p;
    size_t base = (size_t)blockIdx.x * 1024 + threadIdx.x;
    int4 v[4];
#pragma unroll
    for (int j = 0; j < 4; j++) {
        size_t i = base + j * 256;
        if (i < n4) v[j] = ((const int4*)q)[i];
    }
#pragma unroll
    for (int j = 0; j < 4; j++) {
        size_t i = base + j * 256;
        if (i < n4) {
            ((__half2*)g_w)[i * 2 + 0] =
                __floats2half2_rn((float)v[j].x - zp, (float)v[j].y - zp);
            ((__half2*)g_w)[i * 2 + 1] =
                __floats2half2_rn((float)v[j].z - zp, (float)v[j].w - zp);
        }
    }
}

// ---------------------------------------------------------------------------
// Helpers
// ---------------------------------------------------------------------------
__device__ __forceinline__ void cp_async_16(uint32_t smem, const void* g) {
    asm volatile("cp.async.cg.shared.global [%0], [%1], 16;\n" :: "r"(smem), "l"(g));
}
__device__ __forceinline__ void cp_commit() {
    asm volatile("cp.async.commit_group;\n" ::);
}

// ---------------------------------------------------------------------------
// HMMA GEMM: out[M,N] = scale * (Xh[M,K] @ Wh[N,K]^T) + bias[n]
// CTA 128x128 (256 thr, 8 warps of 64x32), BK=64, 3 stages, 2 CTAs/SM,
// one barrier per kt, prefetch distance 2. (Round-9 mainloop, verbatim.)
// ---------------------------------------------------------------------------
__global__ __launch_bounds__(256, 2)
void gemm_kernel(const float* __restrict__ scale_p,
                 const float* __restrict__ bias,
                 float* __restrict__ out) {
    extern __shared__ char dsm[];
    const uint32_t sm_base = (uint32_t)__cvta_generic_to_shared(dsm);

    const int tid  = threadIdx.x;
    const int lane = tid & 31;
    const int warp = tid >> 5;
    const int wm = warp & 1;     // 0..1 -> 64-row slices
    const int wn = warp >> 1;    // 0..3 -> 32-col slices

    const int bid   = blockIdx.x;
    const int mTile = bid & (M_TOT / BM - 1);   // 32 m-tiles, fastest
    const int nTile = bid >> 5;                 // 128 n-tiles
    const int m0 = mTile * BM;
    const int n0 = nTile * BN;

    float acc[4][4][4];
#pragma unroll
    for (int i = 0; i < 4; i++)
#pragma unroll
        for (int j = 0; j < 4; j++)
#pragma unroll
            for (int k = 0; k < 4; k++) acc[i][j][k] = 0.f;

    const __half* gA = g_x + (size_t)m0 * K_TOT;
    const __half* gB = g_w + (size_t)n0 * K_TOT;

    // Per-thread load coords (16B chunks). A: 1024 chunks, B: 1024 chunks; 256 thr.
    const int ldRow = tid >> 3, ldCc = tid & 7;
    auto load_tile = [&](int kt, int st) {
        const int kh0 = kt * BK;
        const uint32_t aBase = sm_base + st * STAGE_BYTES;
        const uint32_t bBase = aBase + A_STAGE_BYTES;
#pragma unroll
        for (int i = 0; i < 4; i++) {       // A: 128 rows x 8 chunks / 256 thr
            int row = ldRow + i * 32;
            cp_async_16(aBase + row * (LDSH * 2) + ldCc * 16,
                        gA + (size_t)row * K_TOT + kh0 + ldCc * 8);
        }
#pragma unroll
        for (int i = 0; i < 4; i++) {       // B: 128 rows x 8 chunks / 256 thr
            int row = ldRow + i * 32;
            cp_async_16(bBase + row * (LDSH * 2) + ldCc * 16,
                        gB + (size_t)row * K_TOT + kh0 + ldCc * 8);
        }
        cp_commit();
    };

    // Prologue: fill 2 stages (prefetch distance 2)
    load_tile(0, 0);
    load_tile(1, 1);

    // ldmatrix per-thread base offsets (bytes), excluding stage/ks/im offsets
    const uint32_t aLdBase =
        (uint32_t)((wm * 64 + (lane & 15)) * (LDSH * 2) + (lane >> 4) * 16);
    const int bl = lane & 15;
    const uint32_t bLdBase =
        (uint32_t)((wn * 32 + (bl & 7)) * (LDSH * 2) + (bl >> 3) * 16);

    int st = 0;     // stage being consumed
    int pst = 2;    // stage to prefetch into

    for (int kt = 0; kt < NKT; kt++) {
        // Tile kt's loads done (allow 1 newer group outstanding)
        asm volatile("cp.async.wait_group 1;\n" ::);
        __syncthreads();

        // Prefetch kt+2 into stage pst (== stage consumed at kt-1; its reads
        // finished before this iteration's barrier).
        if (kt + 2 < NKT) load_tile(kt + 2, pst);
        else cp_commit();   // keep group accounting uniform

        const uint32_t aStage = sm_base + st * STAGE_BYTES;
        const uint32_t bStage = aStage + A_STAGE_BYTES;

#pragma unroll
        for (int ks = 0; ks < 4; ks++) {
            uint32_t a[4][4];
            uint32_t b[4][2];
#pragma unroll
            for (int im = 0; im < 4; im++) {
                uint32_t addr = aStage + aLdBase + im * 16 * (LDSH * 2) + ks * 32;
                asm volatile("ldmatrix.sync.aligned.m8n8.x4.shared.b16 {%0,%1,%2,%3}, [%4];\n"
                             : "=r"(a[im][0]), "=r"(a[im][1]), "=r"(a[im][2]), "=r"(a[im][3])
                             : "r"(addr));
            }
#pragma unroll
            for (int in_ = 0; in_ < 4; in_++) {
                uint32_t addr = bStage + bLdBase + in_ * 8 * (LDSH * 2) + ks * 32;
                asm volatile("ldmatrix.sync.aligned.m8n8.x2.shared.b16 {%0,%1}, [%2];\n"
                             : "=r"(b[in_][0]), "=r"(b[in_][1])
                             : "r"(addr));
            }
#pragma unroll
            for (int im = 0; im < 4; im++) {
#pragma unroll
                for (int in_ = 0; in_ < 4; in_++) {
                    asm volatile(
                        "mma.sync.aligned.m16n8k16.row.col.f32.f16.f16.f32 "
                        "{%0,%1,%2,%3}, {%4,%5,%6,%7}, {%8,%9}, {%0,%1,%2,%3};\n"
                        : "+f"(acc[im][in_][0]), "+f"(acc[im][in_][1]),
                          "+f"(acc[im][in_][2]), "+f"(acc[im][in_][3])
                        : "r"(a[im][0]), "r"(a[im][1]), "r"(a[im][2]), "r"(a[im][3]),
                          "r"(b[in_][0]), "r"(b[in_][1]));
                }
            }
        }

        st  = (st  == NSTAGE - 1) ? 0 : st + 1;
        pst = (pst == NSTAGE - 1) ? 0 : pst + 1;
    }

    // Epilogue: out = scale*acc + bias
    const float s = *scale_p;
    const int mBase = m0 + wm * 64;
    const int nBase = n0 + wn * 32;
#pragma unroll
    for (int im = 0; im < 4; im++) {
#pragma unroll
        for (int in_ = 0; in_ < 4; in_++) {
            int row = mBase + im * 16 + (lane >> 2);
            int col = nBase + in_ * 8 + (lane & 3) * 2;
            float2 bv = *(const float2*)&bias[col];
            float2 o0 = make_float2(s * acc[im][in_][0] + bv.x,
                                    s * acc[im][in_][1] + bv.y);
            float2 o1 = make_float2(s * acc[im][in_][2] + bv.x,
                                    s * acc[im][in_][3] + bv.y);
            *(float2*)&out[(size_t)row * N_TOT + col] = o0;
            *(float2*)&out[(size_t)(row + 8) * N_TOT + col] = o1;
        }
    }
}

// ---------------------------------------------------------------------------
// Launch
// ---------------------------------------------------------------------------
extern "C" void kernel_launch(void* const* d_in, const int* in_sizes, int n_in,
                              void* d_out, int out_size) {
    const float* x     = (const float*)d_in[0];
    const int*   wq    = (const int*)d_in[1];
    const float* scale = (const float*)d_in[2];
    const float* zp    = (const float*)d_in[3];
    const float* bias  = (const float*)d_in[4];
    float* out = (float*)d_out;

    cudaFuncSetAttribute(gemm_kernel, cudaFuncAttributeMaxDynamicSharedMemorySize,
                         DSMEM_BYTES);

    {
        size_t n4 = (size_t)M_TOT * K_TOT / 4;           // 4M chunks, 1024/block
        conv_x_kernel<<<(unsigned)((n4 + 1023) / 1024), 256>>>(x);
    }
    {
        size_t n4 = (size_t)N_TOT * K_TOT / 4;           // 16M chunks, 1024/block
        conv_w_kernel<<<(unsigned)((n4 + 1023) / 1024), 256>>>(wq, zp);
    }
    {
        unsigned grid = (M_TOT / BM) * (N_TOT / BN);     // 32*128 = 4096
        gemm_kernel<<<grid, 256, DSMEM_BYTES>>>(scale, bias, out);
    }
}